// round 15
// baseline (speedup 1.0000x reference)
#include <cuda_runtime.h>
#include <cuda_bf16.h>
#include <cuda_fp16.h>
#include <mma.h>
using namespace nvcuda;

#define NN   100000
#define NNP  100096   // padded to 128-node tiles: 782*128
#define NE   1600000
#define INF_ 128
#define OUTF 64
#define TILE_M 128
#define NBLK ((NN + TILE_M - 1) / TILE_M)   // 782
#define CAP  64
#define MAX_OVF 65536
#define PBLK ((NE / 2 + 255) / 256)         // placement blocks (2 edges/thread)
#define WBLK 64                             // weight-prep blocks

__device__ __align__(16) __half g_support_h[(size_t)NNP * OUTF];  // fp16 support
__device__ float g_resid[(size_t)NNP * OUTF];
__device__ __align__(16) __nv_bfloat16 g_whi[128 * 128];
__device__ __align__(16) __nv_bfloat16 g_wlo[128 * 128];
__device__ int  g_cnt[NNP + 1];             // [NNP] = overflow counter
__device__ int  g_ovf[MAX_OVF];
__device__ int2 g_ell[(size_t)NNP * CAP];   // {src*16 (uint2 row units), w bits}

// ---------------------------------------------------------------------------
// Kernel 1: ELL placement (2 edges/thread — measured best) + weight split
// prep (last WBLK blocks). No smem; both streaming preludes.
// ---------------------------------------------------------------------------
__device__ __forceinline__ void place_one(int e, const int* __restrict__ src,
                                          const int* __restrict__ dst, float w) {
  int d = __ldg(dst + e);
  int s = __ldg(src + e);
  int pos = atomicAdd(&g_cnt[d], 1);
  if (pos < CAP) {
    g_ell[(size_t)d * CAP + pos] = make_int2(s * (OUTF / 4), __float_as_int(w));
  } else {
    int o = atomicAdd(&g_cnt[NNP], 1);
    if (o < MAX_OVF) g_ovf[o] = e;
  }
}

__global__ void __launch_bounds__(256) place_prep_kernel(
    const int* __restrict__ src, const int* __restrict__ dst,
    const float* __restrict__ ew,
    const float* __restrict__ w, const float* __restrict__ rw) {
  unsigned b = blockIdx.x;
  if (b < PBLK) {
    unsigned e0 = b * 512u + threadIdx.x;
    unsigned e1 = e0 + 256u;
    float w0 = (e0 < NE) ? __ldg(ew + e0) : 0.f;
    float w1 = (e1 < NE) ? __ldg(ew + e1) : 0.f;
    if (e0 < NE) place_one((int)e0, src, dst, w0);
    if (e1 < NE) place_one((int)e1, src, dst, w1);
  } else {
    int i = (int)(b - PBLK) * 256 + threadIdx.x;
    if (i >= 128 * 128) return;
    int k = i >> 7, f = i & 127;
    float v = (f < 64) ? w[k * 64 + f] : rw[(f - 64) * 128 + k];
    __nv_bfloat16 h = __float2bfloat16(v);
    g_whi[i] = h;
    g_wlo[i] = __float2bfloat16(v - __bfloat162float(h));
  }
}

// ---------------------------------------------------------------------------
// Kernel 2: WMMA split-bf16 combined GEMM (support | resid).
// 128 nodes/block, 512 threads = 16 warps (4 m x 4 n), 3 passes.
// K split into two 64-k chunks for x staging -> smem 106.5 KB -> 2 blocks/SM.
// Support columns stored fp16 via smem staging (smem reused post-MMA).
// ---------------------------------------------------------------------------
#define LDW 136
#define LDXC 72
#define SM_WHI 0
#define SM_WLO (128 * LDW)
#define SM_XHI (2 * 128 * LDW)
#define SM_XLO (2 * 128 * LDW + 128 * LDXC)
#define GEMM_SMEM ((2 * 128 * LDW + 2 * 128 * LDXC) * 2)   // 106496 B
#define LDS_ 72   // fp32 staging stride (288B rows, 16B-aligned)

__global__ void __launch_bounds__(512) gemm_kernel(const float* __restrict__ x) {
  extern __shared__ __nv_bfloat16 sm[];
  __nv_bfloat16* whi = sm + SM_WHI;
  __nv_bfloat16* wlo = sm + SM_WLO;
  __nv_bfloat16* xhi = sm + SM_XHI;
  __nv_bfloat16* xlo = sm + SM_XLO;
  const int tid = threadIdx.x;
  const int n0 = blockIdx.x * TILE_M;

  // Stage pre-split weights (2048 uint4 per array), full K resident
  {
    const uint4* sh = (const uint4*)g_whi;
    const uint4* sl = (const uint4*)g_wlo;
#pragma unroll
    for (int rep = 0; rep < 4; rep++) {
      int i = tid + rep * 512;
      int r = i >> 4, c = i & 15;
      *(uint4*)(whi + r * LDW + c * 8) = sh[i];
      *(uint4*)(wlo + r * LDW + c * 8) = sl[i];
    }
  }

  const int wid = tid >> 5;
  const int wm = wid & 3;       // node 32-tile (0..3)
  const int wn = wid >> 2;      // feature 32-tile (0..3)

  wmma::fragment<wmma::accumulator, 16, 16, 16, float> acc[2][2];
#pragma unroll
  for (int i = 0; i < 2; i++)
#pragma unroll
    for (int j = 0; j < 2; j++) wmma::fill_fragment(acc[i][j], 0.f);

#pragma unroll
  for (int kc = 0; kc < 2; kc++) {
    __syncthreads();
    // Stage x chunk (128 nodes x 16 float4 = 64 k's), split hi/lo
#pragma unroll
    for (int rep = 0; rep < 4; rep++) {
      int i = tid + rep * 512;               // 2048 float4
      int node = i >> 4, c = i & 15;
      int gn = n0 + node;
      if (gn >= NN) gn = NN - 1;
      float4 v = *(const float4*)(x + (size_t)gn * INF_ + kc * 64 + c * 4);
      __nv_bfloat16 h0 = __float2bfloat16(v.x), h1 = __float2bfloat16(v.y);
      __nv_bfloat16 h2 = __float2bfloat16(v.z), h3 = __float2bfloat16(v.w);
      __nv_bfloat16 l0 = __float2bfloat16(v.x - __bfloat162float(h0));
      __nv_bfloat16 l1 = __float2bfloat16(v.y - __bfloat162float(h1));
      __nv_bfloat16 l2 = __float2bfloat16(v.z - __bfloat162float(h2));
      __nv_bfloat16 l3 = __float2bfloat16(v.w - __bfloat162float(h3));
      __nv_bfloat162* ph = (__nv_bfloat162*)(xhi + node * LDXC + c * 4);
      __nv_bfloat162* pl = (__nv_bfloat162*)(xlo + node * LDXC + c * 4);
      ph[0] = __nv_bfloat162(h0, h1); ph[1] = __nv_bfloat162(h2, h3);
      pl[0] = __nv_bfloat162(l0, l1); pl[1] = __nv_bfloat162(l2, l3);
    }
    __syncthreads();

#pragma unroll
    for (int k = 0; k < 64; k += 16) {
      wmma::fragment<wmma::matrix_a, 16, 16, 16, __nv_bfloat16, wmma::row_major> ahi[2], alo[2];
      wmma::fragment<wmma::matrix_b, 16, 16, 16, __nv_bfloat16, wmma::row_major> bhi[2], blo[2];
#pragma unroll
      for (int i = 0; i < 2; i++) {
        wmma::load_matrix_sync(ahi[i], xhi + (wm * 32 + i * 16) * LDXC + k, LDXC);
        wmma::load_matrix_sync(alo[i], xlo + (wm * 32 + i * 16) * LDXC + k, LDXC);
      }
#pragma unroll
      for (int j = 0; j < 2; j++) {
        wmma::load_matrix_sync(bhi[j], whi + (kc * 64 + k) * LDW + wn * 32 + j * 16, LDW);
        wmma::load_matrix_sync(blo[j], wlo + (kc * 64 + k) * LDW + wn * 32 + j * 16, LDW);
      }
#pragma unroll
      for (int i = 0; i < 2; i++)
#pragma unroll
        for (int j = 0; j < 2; j++) {
          wmma::mma_sync(acc[i][j], ahi[i], bhi[j], acc[i][j]);
          wmma::mma_sync(acc[i][j], ahi[i], blo[j], acc[i][j]);
          wmma::mma_sync(acc[i][j], alo[i], bhi[j], acc[i][j]);
        }
    }
  }

  __syncthreads();   // smem fully free now; reuse as fp32 staging
  float* stage = (float*)sm;   // [128][LDS_]

#pragma unroll
  for (int i = 0; i < 2; i++)
#pragma unroll
    for (int j = 0; j < 2; j++) {
      int rloc = wm * 32 + i * 16;
      int col = wn * 32 + j * 16;
      if (col < 64) {
        wmma::store_matrix_sync(stage + rloc * LDS_ + col, acc[i][j], LDS_,
                                wmma::mem_row_major);
      } else {
        wmma::store_matrix_sync(g_resid + (size_t)(n0 + rloc) * OUTF + (col - 64),
                                acc[i][j], OUTF, wmma::mem_row_major);
      }
    }
  __syncthreads();

  // Convert staged support to fp16: 2048 uint2 writes (4 halves each)
  uint2* suph = (uint2*)g_support_h;
#pragma unroll
  for (int rep = 0; rep < 4; rep++) {
    int i = tid + rep * 512;        // 0..2047
    int r = i >> 4, c = i & 15;
    float4 v = *(const float4*)(stage + r * LDS_ + c * 4);
    __half2 h01 = __floats2half2_rn(v.x, v.y);
    __half2 h23 = __floats2half2_rn(v.z, v.w);
    uint2 o;
    o.x = *(unsigned*)&h01;
    o.y = *(unsigned*)&h23;
    suph[(size_t)(n0 + r) * 16 + c] = o;
  }
}

// ---------------------------------------------------------------------------
// Kernel 3: fused gather + finalize. 16 lanes/node, fp16 support rows
// (uint2 = 4 halves per lane -> 128B/edge), MLP=8, broadcast-LDG ELL.
// ---------------------------------------------------------------------------
__global__ void __launch_bounds__(256) gather_finalize(
    float* __restrict__ out, const float* __restrict__ bias,
    const float* __restrict__ gamma, const float* __restrict__ beta,
    const float* __restrict__ res_b,
    const int* __restrict__ src, const int* __restrict__ dst,
    const float* __restrict__ ew) {
  unsigned t = blockIdx.x * 256u + threadIdx.x;
  unsigned n = t >> 4;
  unsigned q = t & 15;
  const unsigned gmask = 0xffffu << (threadIdx.x & 16);

  int deg_raw = g_cnt[n];
  int deg = deg_raw > CAP ? CAP : deg_raw;

  float4 acc = make_float4(0.f, 0.f, 0.f, 0.f);
  const int2* ellrow = g_ell + (size_t)n * CAP;
  const uint2* suph = (const uint2*)g_support_h;

  for (int base = 0; base < deg; base += 8) {
    int2 e[8];
#pragma unroll
    for (int u = 0; u < 8; u++) {
      int idx = base + u;
      e[u] = (idx < deg) ? __ldg(ellrow + idx) : make_int2(0, 0);
    }
    uint2 raw[8];
#pragma unroll
    for (int u = 0; u < 8; u++)
      raw[u] = __ldg(suph + (unsigned)(e[u].x + q));
#pragma unroll
    for (int u = 0; u < 8; u++) {
      float w = __int_as_float(e[u].y);    // 0 for padded entries
      float2 v01 = __half22float2(*(const __half2*)&raw[u].x);
      float2 v23 = __half22float2(*(const __half2*)&raw[u].y);
      acc.x = fmaf(w, v01.x, acc.x);
      acc.y = fmaf(w, v01.y, acc.y);
      acc.z = fmaf(w, v23.x, acc.z);
      acc.w = fmaf(w, v23.y, acc.w);
    }
  }

  if (deg_raw > CAP) {          // essentially never taken
    int m = g_cnt[NNP];
    if (m > MAX_OVF) m = MAX_OVF;
    for (int i = 0; i < m; i++) {
      int e = g_ovf[i];
      if ((unsigned)__ldg(dst + e) == n) {
        float w = __ldg(ew + e);
        uint2 raw = __ldg(suph + (unsigned)(__ldg(src + e) * (OUTF / 4) + q));
        float2 v01 = __half22float2(*(const __half2*)&raw.x);
        float2 v23 = __half22float2(*(const __half2*)&raw.y);
        acc.x = fmaf(w, v01.x, acc.x); acc.y = fmaf(w, v01.y, acc.y);
        acc.z = fmaf(w, v23.x, acc.z); acc.w = fmaf(w, v23.y, acc.w);
      }
    }
  }

  // finalize
  float4 b = *(const float4*)(bias + q * 4);
  acc.x += b.x; acc.y += b.y; acc.z += b.z; acc.w += b.w;

  float s  = acc.x + acc.y + acc.z + acc.w;
  float s2 = acc.x * acc.x + acc.y * acc.y + acc.z * acc.z + acc.w * acc.w;
#pragma unroll
  for (int m = 8; m >= 1; m >>= 1) {
    s  += __shfl_xor_sync(gmask, s, m, 16);
    s2 += __shfl_xor_sync(gmask, s2, m, 16);
  }
  float mu  = s * (1.f / 64.f);
  float var = s2 * (1.f / 64.f) - mu * mu;
  float inv = rsqrtf(var + 1e-5f);

  float4 g  = *(const float4*)(gamma + q * 4);
  float4 be = *(const float4*)(beta + q * 4);
  float4 r  = *(const float4*)(g_resid + (size_t)n * OUTF + q * 4);
  float4 rb = *(const float4*)(res_b + q * 4);

  acc.x = fmaxf((acc.x - mu) * inv * g.x + be.x, 0.f) + r.x + rb.x;
  acc.y = fmaxf((acc.y - mu) * inv * g.y + be.y, 0.f) + r.y + rb.y;
  acc.z = fmaxf((acc.z - mu) * inv * g.z + be.z, 0.f) + r.z + rb.z;
  acc.w = fmaxf((acc.w - mu) * inv * g.w + be.w, 0.f) + r.w + rb.w;

  *(float4*)(out + (size_t)n * OUTF + q * 4) = acc;
}

// ---------------------------------------------------------------------------
extern "C" void kernel_launch(void* const* d_in, const int* in_sizes, int n_in,
                              void* d_out, int out_size) {
  const float* x      = (const float*)d_in[0];
  const float* weight = (const float*)d_in[1];
  const float* bias   = (const float*)d_in[2];
  const float* gamma  = (const float*)d_in[3];
  const float* beta   = (const float*)d_in[4];
  const float* res_w  = (const float*)d_in[5];
  const float* res_b  = (const float*)d_in[6];
  const float* ew     = (const float*)d_in[7];
  const int*   esrc   = (const int*)d_in[8];
  const int*   edst   = (const int*)d_in[9];
  float* out = (float*)d_out;

  cudaFuncSetAttribute(gemm_kernel,
                       cudaFuncAttributeMaxDynamicSharedMemorySize, GEMM_SMEM);

  void* cntp = nullptr;
  cudaGetSymbolAddress(&cntp, g_cnt);
  cudaMemsetAsync(cntp, 0, (NNP + 1) * sizeof(int), 0);

  place_prep_kernel<<<PBLK + WBLK, 256>>>(esrc, edst, ew, weight, res_w);

  gemm_kernel<<<NBLK, 512, GEMM_SMEM>>>(x);

  gather_finalize<<<(NN * 16) / 256, 256>>>(out, bias, gamma, beta, res_b,
                                            esrc, edst, ew);
}

// round 16
// speedup vs baseline: 1.0392x; 1.0392x over previous
#include <cuda_runtime.h>
#include <cuda_bf16.h>
#include <cuda_fp16.h>
#include <mma.h>
using namespace nvcuda;

#define NN   100000
#define NNP  100096   // padded to 128-node tiles: 782*128
#define NE   1600000
#define INF_ 128
#define OUTF 64
#define TILE_M 128
#define NBLK ((NN + TILE_M - 1) / TILE_M)   // 782
#define CAP  64
#define MAX_OVF 65536
#define PBLK ((NE / 2 + 255) / 256)         // placement blocks (2 edges/thread)
#define WBLK 64                             // weight-prep blocks

__device__ __align__(16) __half g_support_h[(size_t)NNP * OUTF];  // fp16 support
__device__ float g_resid[(size_t)NNP * OUTF];
__device__ __align__(16) __nv_bfloat16 g_whi[128 * 128];
__device__ __align__(16) __nv_bfloat16 g_wlo[128 * 128];
__device__ int  g_cnt[NNP + 1];             // [NNP] = overflow counter
__device__ int  g_ovf[MAX_OVF];
__device__ int2 g_ell[(size_t)NNP * CAP];   // {src*8 (uint4 row units), w bits}

// ---------------------------------------------------------------------------
// Kernel 1: ELL placement (2 edges/thread — measured best) + weight split
// prep (last WBLK blocks). No smem; both streaming preludes.
// ---------------------------------------------------------------------------
__device__ __forceinline__ void place_one(int e, const int* __restrict__ src,
                                          const int* __restrict__ dst, float w) {
  int d = __ldg(dst + e);
  int s = __ldg(src + e);
  int pos = atomicAdd(&g_cnt[d], 1);
  if (pos < CAP) {
    g_ell[(size_t)d * CAP + pos] = make_int2(s * (OUTF / 8), __float_as_int(w));
  } else {
    int o = atomicAdd(&g_cnt[NNP], 1);
    if (o < MAX_OVF) g_ovf[o] = e;
  }
}

__global__ void __launch_bounds__(256) place_prep_kernel(
    const int* __restrict__ src, const int* __restrict__ dst,
    const float* __restrict__ ew,
    const float* __restrict__ w, const float* __restrict__ rw) {
  unsigned b = blockIdx.x;
  if (b < PBLK) {
    unsigned e0 = b * 512u + threadIdx.x;
    unsigned e1 = e0 + 256u;
    float w0 = (e0 < NE) ? __ldg(ew + e0) : 0.f;
    float w1 = (e1 < NE) ? __ldg(ew + e1) : 0.f;
    if (e0 < NE) place_one((int)e0, src, dst, w0);
    if (e1 < NE) place_one((int)e1, src, dst, w1);
  } else {
    int i = (int)(b - PBLK) * 256 + threadIdx.x;
    if (i >= 128 * 128) return;
    int k = i >> 7, f = i & 127;
    float v = (f < 64) ? w[k * 64 + f] : rw[(f - 64) * 128 + k];
    __nv_bfloat16 h = __float2bfloat16(v);
    g_whi[i] = h;
    g_wlo[i] = __float2bfloat16(v - __bfloat162float(h));
  }
}

// ---------------------------------------------------------------------------
// Kernel 2: WMMA split-bf16 combined GEMM (support | resid). R14 form:
// full-K staging, 128 nodes/block, 512 threads = 16 warps (4m x 4n),
// 3 passes (hh, hl, lh), K=128. Support stored fp16 via smem staging.
// ---------------------------------------------------------------------------
#define LDX 136
#define LDW 136
#define SM_XHI 0
#define SM_XLO (128 * LDX)
#define SM_WHI (2 * 128 * LDX)
#define SM_WLO (2 * 128 * LDX + 128 * LDW)
#define GEMM_SMEM ((2 * 128 * LDX + 2 * 128 * LDW) * 2)   // 139264 B
#define LDS_ 72   // fp32 staging stride

__global__ void __launch_bounds__(512) gemm_kernel(const float* __restrict__ x) {
  extern __shared__ __nv_bfloat16 sm[];
  __nv_bfloat16* xhi = sm + SM_XHI;
  __nv_bfloat16* xlo = sm + SM_XLO;
  __nv_bfloat16* whi = sm + SM_WHI;
  __nv_bfloat16* wlo = sm + SM_WLO;
  const int tid = threadIdx.x;
  const int n0 = blockIdx.x * TILE_M;

  {
    const uint4* sh = (const uint4*)g_whi;
    const uint4* sl = (const uint4*)g_wlo;
#pragma unroll
    for (int rep = 0; rep < 4; rep++) {
      int i = tid + rep * 512;
      int r = i >> 4, c = i & 15;
      *(uint4*)(whi + r * LDW + c * 8) = sh[i];
      *(uint4*)(wlo + r * LDW + c * 8) = sl[i];
    }
  }
#pragma unroll
  for (int rep = 0; rep < 8; rep++) {
    int i = tid + rep * 512;                 // 4096 float4
    int node = i >> 5, c = i & 31;
    int gn = n0 + node;
    if (gn >= NN) gn = NN - 1;
    float4 v = *(const float4*)(x + (size_t)gn * INF_ + c * 4);
    __nv_bfloat16 h0 = __float2bfloat16(v.x), h1 = __float2bfloat16(v.y);
    __nv_bfloat16 h2 = __float2bfloat16(v.z), h3 = __float2bfloat16(v.w);
    __nv_bfloat16 l0 = __float2bfloat16(v.x - __bfloat162float(h0));
    __nv_bfloat16 l1 = __float2bfloat16(v.y - __bfloat162float(h1));
    __nv_bfloat16 l2 = __float2bfloat16(v.z - __bfloat162float(h2));
    __nv_bfloat16 l3 = __float2bfloat16(v.w - __bfloat162float(h3));
    __nv_bfloat162* ph = (__nv_bfloat162*)(xhi + node * LDX + c * 4);
    __nv_bfloat162* pl = (__nv_bfloat162*)(xlo + node * LDX + c * 4);
    ph[0] = __nv_bfloat162(h0, h1); ph[1] = __nv_bfloat162(h2, h3);
    pl[0] = __nv_bfloat162(l0, l1); pl[1] = __nv_bfloat162(l2, l3);
  }
  __syncthreads();

  const int wid = tid >> 5;
  const int wm = wid & 3;
  const int wn = wid >> 2;

  wmma::fragment<wmma::accumulator, 16, 16, 16, float> acc[2][2];
#pragma unroll
  for (int i = 0; i < 2; i++)
#pragma unroll
    for (int j = 0; j < 2; j++) wmma::fill_fragment(acc[i][j], 0.f);

#pragma unroll
  for (int k = 0; k < 128; k += 16) {
    wmma::fragment<wmma::matrix_a, 16, 16, 16, __nv_bfloat16, wmma::row_major> ahi[2], alo[2];
    wmma::fragment<wmma::matrix_b, 16, 16, 16, __nv_bfloat16, wmma::row_major> bhi[2], blo[2];
#pragma unroll
    for (int i = 0; i < 2; i++) {
      wmma::load_matrix_sync(ahi[i], xhi + (wm * 32 + i * 16) * LDX + k, LDX);
      wmma::load_matrix_sync(alo[i], xlo + (wm * 32 + i * 16) * LDX + k, LDX);
    }
#pragma unroll
    for (int j = 0; j < 2; j++) {
      wmma::load_matrix_sync(bhi[j], whi + k * LDW + wn * 32 + j * 16, LDW);
      wmma::load_matrix_sync(blo[j], wlo + k * LDW + wn * 32 + j * 16, LDW);
    }
#pragma unroll
    for (int i = 0; i < 2; i++)
#pragma unroll
      for (int j = 0; j < 2; j++) {
        wmma::mma_sync(acc[i][j], ahi[i], bhi[j], acc[i][j]);
        wmma::mma_sync(acc[i][j], ahi[i], blo[j], acc[i][j]);
        wmma::mma_sync(acc[i][j], alo[i], bhi[j], acc[i][j]);
      }
  }

  __syncthreads();   // x smem no longer needed; reuse as fp32 staging
  float* stage = (float*)sm;   // [128][LDS_]

#pragma unroll
  for (int i = 0; i < 2; i++)
#pragma unroll
    for (int j = 0; j < 2; j++) {
      int rloc = wm * 32 + i * 16;
      int col = wn * 32 + j * 16;
      if (col < 64) {
        wmma::store_matrix_sync(stage + rloc * LDS_ + col, acc[i][j], LDS_,
                                wmma::mem_row_major);
      } else {
        wmma::store_matrix_sync(g_resid + (size_t)(n0 + rloc) * OUTF + (col - 64),
                                acc[i][j], OUTF, wmma::mem_row_major);
      }
    }
  __syncthreads();

  // Convert staged support to fp16: 1024 uint4 writes (8 halves each)
  uint4* suph = (uint4*)g_support_h;
#pragma unroll
  for (int rep = 0; rep < 2; rep++) {
    int i = tid + rep * 512;        // 0..1023
    int r = i >> 3, c = i & 7;
    float4 v0 = *(const float4*)(stage + r * LDS_ + c * 8);
    float4 v1 = *(const float4*)(stage + r * LDS_ + c * 8 + 4);
    __half2 h01 = __floats2half2_rn(v0.x, v0.y);
    __half2 h23 = __floats2half2_rn(v0.z, v0.w);
    __half2 h45 = __floats2half2_rn(v1.x, v1.y);
    __half2 h67 = __floats2half2_rn(v1.z, v1.w);
    uint4 o;
    o.x = *(unsigned*)&h01;
    o.y = *(unsigned*)&h23;
    o.z = *(unsigned*)&h45;
    o.w = *(unsigned*)&h67;
    suph[(size_t)(n0 + r) * 8 + c] = o;
  }
}

// ---------------------------------------------------------------------------
// Kernel 3: fused gather + finalize. 8 lanes/node (4 nodes per warp).
// uint4 loads (8 halves/lane -> 128B/edge), MLP=4, broadcast-LDG ELL.
// ---------------------------------------------------------------------------
__global__ void __launch_bounds__(256) gather_finalize(
    float* __restrict__ out, const float* __restrict__ bias,
    const float* __restrict__ gamma, const float* __restrict__ beta,
    const float* __restrict__ res_b,
    const int* __restrict__ src, const int* __restrict__ dst,
    const float* __restrict__ ew) {
  unsigned t = blockIdx.x * 256u + threadIdx.x;
  unsigned n = t >> 3;
  unsigned q = t & 7;
  const unsigned gmask = 0xffu << (threadIdx.x & 24);

  int deg_raw = g_cnt[n];
  int deg = deg_raw > CAP ? CAP : deg_raw;

  float a[8];
#pragma unroll
  for (int i = 0; i < 8; i++) a[i] = 0.f;

  const int2* ellrow = g_ell + (size_t)n * CAP;
  const uint4* suph = (const uint4*)g_support_h;

  for (int base = 0; base < deg; base += 4) {
    int2 e[4];
#pragma unroll
    for (int u = 0; u < 4; u++) {
      int idx = base + u;
      e[u] = (idx < deg) ? __ldg(ellrow + idx) : make_int2(0, 0);
    }
    uint4 raw[4];
#pragma unroll
    for (int u = 0; u < 4; u++)
      raw[u] = __ldg(suph + (unsigned)(e[u].x + q));
#pragma unroll
    for (int u = 0; u < 4; u++) {
      float w = __int_as_float(e[u].y);    // 0 for padded entries
      float2 v01 = __half22float2(*(const __half2*)&raw[u].x);
      float2 v23 = __half22float2(*(const __half2*)&raw[u].y);
      float2 v45 = __half22float2(*(const __half2*)&raw[u].z);
      float2 v67 = __half22float2(*(const __half2*)&raw[u].w);
      a[0] = fmaf(w, v01.x, a[0]); a[1] = fmaf(w, v01.y, a[1]);
      a[2] = fmaf(w, v23.x, a[2]); a[3] = fmaf(w, v23.y, a[3]);
      a[4] = fmaf(w, v45.x, a[4]); a[5] = fmaf(w, v45.y, a[5]);
      a[6] = fmaf(w, v67.x, a[6]); a[7] = fmaf(w, v67.y, a[7]);
    }
  }

  if (deg_raw > CAP) {          // essentially never taken
    int m = g_cnt[NNP];
    if (m > MAX_OVF) m = MAX_OVF;
    for (int i = 0; i < m; i++) {
      int e = g_ovf[i];
      if ((unsigned)__ldg(dst + e) == n) {
        float w = __ldg(ew + e);
        uint4 raw = __ldg(suph + (unsigned)(__ldg(src + e) * (OUTF / 8) + q));
        float2 v01 = __half22float2(*(const __half2*)&raw.x);
        float2 v23 = __half22float2(*(const __half2*)&raw.y);
        float2 v45 = __half22float2(*(const __half2*)&raw.z);
        float2 v67 = __half22float2(*(const __half2*)&raw.w);
        a[0] = fmaf(w, v01.x, a[0]); a[1] = fmaf(w, v01.y, a[1]);
        a[2] = fmaf(w, v23.x, a[2]); a[3] = fmaf(w, v23.y, a[3]);
        a[4] = fmaf(w, v45.x, a[4]); a[5] = fmaf(w, v45.y, a[5]);
        a[6] = fmaf(w, v67.x, a[6]); a[7] = fmaf(w, v67.y, a[7]);
      }
    }
  }

  // finalize
  float4 b0 = *(const float4*)(bias + q * 8);
  float4 b1 = *(const float4*)(bias + q * 8 + 4);
  a[0] += b0.x; a[1] += b0.y; a[2] += b0.z; a[3] += b0.w;
  a[4] += b1.x; a[5] += b1.y; a[6] += b1.z; a[7] += b1.w;

  float s = 0.f, s2 = 0.f;
#pragma unroll
  for (int i = 0; i < 8; i++) { s += a[i]; s2 = fmaf(a[i], a[i], s2); }
#pragma unroll
  for (int m = 4; m >= 1; m >>= 1) {
    s  += __shfl_xor_sync(gmask, s, m, 8);
    s2 += __shfl_xor_sync(gmask, s2, m, 8);
  }
  float mu  = s * (1.f / 64.f);
  float var = s2 * (1.f / 64.f) - mu * mu;
  float inv = rsqrtf(var + 1e-5f);

  float4 g0 = *(const float4*)(gamma + q * 8);
  float4 g1 = *(const float4*)(gamma + q * 8 + 4);
  float4 be0 = *(const float4*)(beta + q * 8);
  float4 be1 = *(const float4*)(beta + q * 8 + 4);
  float4 r0 = *(const float4*)(g_resid + (size_t)n * OUTF + q * 8);
  float4 r1 = *(const float4*)(g_resid + (size_t)n * OUTF + q * 8 + 4);
  float4 rb0 = *(const float4*)(res_b + q * 8);
  float4 rb1 = *(const float4*)(res_b + q * 8 + 4);

  float4 o0, o1;
  o0.x = fmaxf((a[0] - mu) * inv * g0.x + be0.x, 0.f) + r0.x + rb0.x;
  o0.y = fmaxf((a[1] - mu) * inv * g0.y + be0.y, 0.f) + r0.y + rb0.y;
  o0.z = fmaxf((a[2] - mu) * inv * g0.z + be0.z, 0.f) + r0.z + rb0.z;
  o0.w = fmaxf((a[3] - mu) * inv * g0.w + be0.w, 0.f) + r0.w + rb0.w;
  o1.x = fmaxf((a[4] - mu) * inv * g1.x + be1.x, 0.f) + r1.x + rb1.x;
  o1.y = fmaxf((a[5] - mu) * inv * g1.y + be1.y, 0.f) + r1.y + rb1.y;
  o1.z = fmaxf((a[6] - mu) * inv * g1.z + be1.z, 0.f) + r1.z + rb1.z;
  o1.w = fmaxf((a[7] - mu) * inv * g1.w + be1.w, 0.f) + r1.w + rb1.w;

  *(float4*)(out + (size_t)n * OUTF + q * 8) = o0;
  *(float4*)(out + (size_t)n * OUTF + q * 8 + 4) = o1;
}

// ---------------------------------------------------------------------------
extern "C" void kernel_launch(void* const* d_in, const int* in_sizes, int n_in,
                              void* d_out, int out_size) {
  const float* x      = (const float*)d_in[0];
  const float* weight = (const float*)d_in[1];
  const float* bias   = (const float*)d_in[2];
  const float* gamma  = (const float*)d_in[3];
  const float* beta   = (const float*)d_in[4];
  const float* res_w  = (const float*)d_in[5];
  const float* res_b  = (const float*)d_in[6];
  const float* ew     = (const float*)d_in[7];
  const int*   esrc   = (const int*)d_in[8];
  const int*   edst   = (const int*)d_in[9];
  float* out = (float*)d_out;

  cudaFuncSetAttribute(gemm_kernel,
                       cudaFuncAttributeMaxDynamicSharedMemorySize, GEMM_SMEM);

  void* cntp = nullptr;
  cudaGetSymbolAddress(&cntp, g_cnt);
  cudaMemsetAsync(cntp, 0, (NNP + 1) * sizeof(int), 0);

  place_prep_kernel<<<PBLK + WBLK, 256>>>(esrc, edst, ew, weight, res_w);

  gemm_kernel<<<NBLK, 512, GEMM_SMEM>>>(x);

  gather_finalize<<<(NN * 8) / 256, 256>>>(out, bias, gamma, beta, res_b,
                                           esrc, edst, ew);
}

// round 17
// speedup vs baseline: 1.0479x; 1.0084x over previous
#include <cuda_runtime.h>
#include <cuda_bf16.h>
#include <cuda_fp16.h>
#include <mma.h>
using namespace nvcuda;

#define NN   100000
#define NNP  100096   // padded to 128-node tiles: 782*128
#define NE   1600000
#define INF_ 128
#define OUTF 64
#define TILE_M 128
#define NBLK ((NN + TILE_M - 1) / TILE_M)   // 782
#define CAP  64
#define MAX_OVF 65536
#define PBLK ((NE / 2 + 255) / 256)         // placement blocks (2 edges/thread)

__device__ __align__(16) __half g_support_h[(size_t)NNP * OUTF];  // fp16 support
__device__ float g_resid[(size_t)NNP * OUTF];
__device__ __align__(16) __nv_bfloat16 g_whi[128 * 128];
__device__ __align__(16) __nv_bfloat16 g_wlo[128 * 128];
__device__ int  g_cnt[NNP + 1];             // [NNP] = overflow counter
__device__ int  g_ovf[MAX_OVF];
__device__ int2 g_ell[(size_t)NNP * CAP];   // {src*16 (uint2 row units), w bits}

// ---------------------------------------------------------------------------
// Kernel A (side stream): ELL placement, 2 edges/thread (measured best).
// ---------------------------------------------------------------------------
__device__ __forceinline__ void place_one(int e, const int* __restrict__ src,
                                          const int* __restrict__ dst, float w) {
  int d = __ldg(dst + e);
  int s = __ldg(src + e);
  int pos = atomicAdd(&g_cnt[d], 1);
  if (pos < CAP) {
    g_ell[(size_t)d * CAP + pos] = make_int2(s * (OUTF / 4), __float_as_int(w));
  } else {
    int o = atomicAdd(&g_cnt[NNP], 1);
    if (o < MAX_OVF) g_ovf[o] = e;
  }
}

__global__ void __launch_bounds__(256) placement_kernel(
    const int* __restrict__ src, const int* __restrict__ dst,
    const float* __restrict__ ew) {
  unsigned e0 = blockIdx.x * 512u + threadIdx.x;
  unsigned e1 = e0 + 256u;
  float w0 = (e0 < NE) ? __ldg(ew + e0) : 0.f;
  float w1 = (e1 < NE) ? __ldg(ew + e1) : 0.f;
  if (e0 < NE) place_one((int)e0, src, dst, w0);
  if (e1 < NE) place_one((int)e1, src, dst, w1);
}

// ---------------------------------------------------------------------------
// Kernel B (main stream): weight split prep.
// ---------------------------------------------------------------------------
__global__ void prep_weights(const float* __restrict__ w,
                             const float* __restrict__ rw) {
  int i = blockIdx.x * blockDim.x + threadIdx.x;
  if (i >= 128 * 128) return;
  int k = i >> 7, f = i & 127;
  float v = (f < 64) ? w[k * 64 + f] : rw[(f - 64) * 128 + k];
  __nv_bfloat16 h = __float2bfloat16(v);
  g_whi[i] = h;
  g_wlo[i] = __float2bfloat16(v - __bfloat162float(h));
}

// ---------------------------------------------------------------------------
// Kernel C (main stream): WMMA split-bf16 combined GEMM (support | resid).
// Full-K staging, 128 nodes/block, 512 threads = 16 warps (4m x 4n),
// 3 passes (hh, hl, lh), K=128. Support stored fp16 via smem staging.
// ---------------------------------------------------------------------------
#define LDX 136
#define LDW 136
#define SM_XHI 0
#define SM_XLO (128 * LDX)
#define SM_WHI (2 * 128 * LDX)
#define SM_WLO (2 * 128 * LDX + 128 * LDW)
#define GEMM_SMEM ((2 * 128 * LDX + 2 * 128 * LDW) * 2)   // 139264 B
#define LDS_ 72   // fp32 staging stride

__global__ void __launch_bounds__(512) gemm_kernel(const float* __restrict__ x) {
  extern __shared__ __nv_bfloat16 sm[];
  __nv_bfloat16* xhi = sm + SM_XHI;
  __nv_bfloat16* xlo = sm + SM_XLO;
  __nv_bfloat16* whi = sm + SM_WHI;
  __nv_bfloat16* wlo = sm + SM_WLO;
  const int tid = threadIdx.x;
  const int n0 = blockIdx.x * TILE_M;

  {
    const uint4* sh = (const uint4*)g_whi;
    const uint4* sl = (const uint4*)g_wlo;
#pragma unroll
    for (int rep = 0; rep < 4; rep++) {
      int i = tid + rep * 512;
      int r = i >> 4, c = i & 15;
      *(uint4*)(whi + r * LDW + c * 8) = sh[i];
      *(uint4*)(wlo + r * LDW + c * 8) = sl[i];
    }
  }
#pragma unroll
  for (int rep = 0; rep < 8; rep++) {
    int i = tid + rep * 512;                 // 4096 float4
    int node = i >> 5, c = i & 31;
    int gn = n0 + node;
    if (gn >= NN) gn = NN - 1;
    float4 v = *(const float4*)(x + (size_t)gn * INF_ + c * 4);
    __nv_bfloat16 h0 = __float2bfloat16(v.x), h1 = __float2bfloat16(v.y);
    __nv_bfloat16 h2 = __float2bfloat16(v.z), h3 = __float2bfloat16(v.w);
    __nv_bfloat16 l0 = __float2bfloat16(v.x - __bfloat162float(h0));
    __nv_bfloat16 l1 = __float2bfloat16(v.y - __bfloat162float(h1));
    __nv_bfloat16 l2 = __float2bfloat16(v.z - __bfloat162float(h2));
    __nv_bfloat16 l3 = __float2bfloat16(v.w - __bfloat162float(h3));
    __nv_bfloat162* ph = (__nv_bfloat162*)(xhi + node * LDX + c * 4);
    __nv_bfloat162* pl = (__nv_bfloat162*)(xlo + node * LDX + c * 4);
    ph[0] = __nv_bfloat162(h0, h1); ph[1] = __nv_bfloat162(h2, h3);
    pl[0] = __nv_bfloat162(l0, l1); pl[1] = __nv_bfloat162(l2, l3);
  }
  __syncthreads();

  const int wid = tid >> 5;
  const int wm = wid & 3;
  const int wn = wid >> 2;

  wmma::fragment<wmma::accumulator, 16, 16, 16, float> acc[2][2];
#pragma unroll
  for (int i = 0; i < 2; i++)
#pragma unroll
    for (int j = 0; j < 2; j++) wmma::fill_fragment(acc[i][j], 0.f);

#pragma unroll
  for (int k = 0; k < 128; k += 16) {
    wmma::fragment<wmma::matrix_a, 16, 16, 16, __nv_bfloat16, wmma::row_major> ahi[2], alo[2];
    wmma::fragment<wmma::matrix_b, 16, 16, 16, __nv_bfloat16, wmma::row_major> bhi[2], blo[2];
#pragma unroll
    for (int i = 0; i < 2; i++) {
      wmma::load_matrix_sync(ahi[i], xhi + (wm * 32 + i * 16) * LDX + k, LDX);
      wmma::load_matrix_sync(alo[i], xlo + (wm * 32 + i * 16) * LDX + k, LDX);
    }
#pragma unroll
    for (int j = 0; j < 2; j++) {
      wmma::load_matrix_sync(bhi[j], whi + k * LDW + wn * 32 + j * 16, LDW);
      wmma::load_matrix_sync(blo[j], wlo + k * LDW + wn * 32 + j * 16, LDW);
    }
#pragma unroll
    for (int i = 0; i < 2; i++)
#pragma unroll
      for (int j = 0; j < 2; j++) {
        wmma::mma_sync(acc[i][j], ahi[i], bhi[j], acc[i][j]);
        wmma::mma_sync(acc[i][j], ahi[i], blo[j], acc[i][j]);
        wmma::mma_sync(acc[i][j], alo[i], bhi[j], acc[i][j]);
      }
  }

  __syncthreads();   // x smem no longer needed; reuse as fp32 staging
  float* stage = (float*)sm;   // [128][LDS_]

#pragma unroll
  for (int i = 0; i < 2; i++)
#pragma unroll
    for (int j = 0; j < 2; j++) {
      int rloc = wm * 32 + i * 16;
      int col = wn * 32 + j * 16;
      if (col < 64) {
        wmma::store_matrix_sync(stage + rloc * LDS_ + col, acc[i][j], LDS_,
                                wmma::mem_row_major);
      } else {
        wmma::store_matrix_sync(g_resid + (size_t)(n0 + rloc) * OUTF + (col - 64),
                                acc[i][j], OUTF, wmma::mem_row_major);
      }
    }
  __syncthreads();

  // Convert staged support to fp16: 2048 uint2 writes (4 halves each)
  uint2* suph = (uint2*)g_support_h;
#pragma unroll
  for (int rep = 0; rep < 4; rep++) {
    int i = tid + rep * 512;        // 0..2047
    int r = i >> 4, c = i & 15;
    float4 v = *(const float4*)(stage + r * LDS_ + c * 4);
    __half2 h01 = __floats2half2_rn(v.x, v.y);
    __half2 h23 = __floats2half2_rn(v.z, v.w);
    uint2 o;
    o.x = *(unsigned*)&h01;
    o.y = *(unsigned*)&h23;
    suph[(size_t)(n0 + r) * 16 + c] = o;
  }
}

// ---------------------------------------------------------------------------
// Kernel D (main stream, after join): fused gather + finalize.
// 16 lanes/node, fp16 support rows (uint2/lane -> 128B/edge), MLP=8.
// ---------------------------------------------------------------------------
__global__ void __launch_bounds__(256) gather_finalize(
    float* __restrict__ out, const float* __restrict__ bias,
    const float* __restrict__ gamma, const float* __restrict__ beta,
    const float* __restrict__ res_b,
    const int* __restrict__ src, const int* __restrict__ dst,
    const float* __restrict__ ew) {
  unsigned t = blockIdx.x * 256u + threadIdx.x;
  unsigned n = t >> 4;
  unsigned q = t & 15;
  const unsigned gmask = 0xffffu << (threadIdx.x & 16);

  int deg_raw = g_cnt[n];
  int deg = deg_raw > CAP ? CAP : deg_raw;

  float4 acc = make_float4(0.f, 0.f, 0.f, 0.f);
  const int2* ellrow = g_ell + (size_t)n * CAP;
  const uint2* suph = (const uint2*)g_support_h;

  for (int base = 0; base < deg; base += 8) {
    int2 e[8];
#pragma unroll
    for (int u = 0; u < 8; u++) {
      int idx = base + u;
      e[u] = (idx < deg) ? __ldg(ellrow + idx) : make_int2(0, 0);
    }
    uint2 raw[8];
#pragma unroll
    for (int u = 0; u < 8; u++)
      raw[u] = __ldg(suph + (unsigned)(e[u].x + q));
#pragma unroll
    for (int u = 0; u < 8; u++) {
      float w = __int_as_float(e[u].y);    // 0 for padded entries
      float2 v01 = __half22float2(*(const __half2*)&raw[u].x);
      float2 v23 = __half22float2(*(const __half2*)&raw[u].y);
      acc.x = fmaf(w, v01.x, acc.x);
      acc.y = fmaf(w, v01.y, acc.y);
      acc.z = fmaf(w, v23.x, acc.z);
      acc.w = fmaf(w, v23.y, acc.w);
    }
  }

  if (deg_raw > CAP) {          // essentially never taken
    int m = g_cnt[NNP];
    if (m > MAX_OVF) m = MAX_OVF;
    for (int i = 0; i < m; i++) {
      int e = g_ovf[i];
      if ((unsigned)__ldg(dst + e) == n) {
        float w = __ldg(ew + e);
        uint2 raw = __ldg(suph + (unsigned)(__ldg(src + e) * (OUTF / 4) + q));
        float2 v01 = __half22float2(*(const __half2*)&raw.x);
        float2 v23 = __half22float2(*(const __half2*)&raw.y);
        acc.x = fmaf(w, v01.x, acc.x); acc.y = fmaf(w, v01.y, acc.y);
        acc.z = fmaf(w, v23.x, acc.z); acc.w = fmaf(w, v23.y, acc.w);
      }
    }
  }

  // finalize
  float4 b = *(const float4*)(bias + q * 4);
  acc.x += b.x; acc.y += b.y; acc.z += b.z; acc.w += b.w;

  float s  = acc.x + acc.y + acc.z + acc.w;
  float s2 = acc.x * acc.x + acc.y * acc.y + acc.z * acc.z + acc.w * acc.w;
#pragma unroll
  for (int m = 8; m >= 1; m >>= 1) {
    s  += __shfl_xor_sync(gmask, s, m, 16);
    s2 += __shfl_xor_sync(gmask, s2, m, 16);
  }
  float mu  = s * (1.f / 64.f);
  float var = s2 * (1.f / 64.f) - mu * mu;
  float inv = rsqrtf(var + 1e-5f);

  float4 g  = *(const float4*)(gamma + q * 4);
  float4 be = *(const float4*)(beta + q * 4);
  float4 r  = *(const float4*)(g_resid + (size_t)n * OUTF + q * 4);
  float4 rb = *(const float4*)(res_b + q * 4);

  acc.x = fmaxf((acc.x - mu) * inv * g.x + be.x, 0.f) + r.x + rb.x;
  acc.y = fmaxf((acc.y - mu) * inv * g.y + be.y, 0.f) + r.y + rb.y;
  acc.z = fmaxf((acc.z - mu) * inv * g.z + be.z, 0.f) + r.z + rb.z;
  acc.w = fmaxf((acc.w - mu) * inv * g.w + be.w, 0.f) + r.w + rb.w;

  *(float4*)(out + (size_t)n * OUTF + q * 4) = acc;
}

// ---------------------------------------------------------------------------
// Launch: graph fork — side stream runs memset(g_cnt)+placement in parallel
// with prep_weights+gemm on the main stream; join before gather.
// Stream/event created once (first, non-captured call); identical graph
// every capture; no device allocations.
// ---------------------------------------------------------------------------
extern "C" void kernel_launch(void* const* d_in, const int* in_sizes, int n_in,
                              void* d_out, int out_size) {
  const float* x      = (const float*)d_in[0];
  const float* weight = (const float*)d_in[1];
  const float* bias   = (const float*)d_in[2];
  const float* gamma  = (const float*)d_in[3];
  const float* beta   = (const float*)d_in[4];
  const float* res_w  = (const float*)d_in[5];
  const float* res_b  = (const float*)d_in[6];
  const float* ew     = (const float*)d_in[7];
  const int*   esrc   = (const int*)d_in[8];
  const int*   edst   = (const int*)d_in[9];
  float* out = (float*)d_out;

  static cudaStream_t s_side = nullptr;
  static cudaEvent_t s_fork = nullptr, s_join = nullptr;
  if (s_side == nullptr) {
    cudaStreamCreateWithFlags(&s_side, cudaStreamNonBlocking);
    cudaEventCreateWithFlags(&s_fork, cudaEventDisableTiming);
    cudaEventCreateWithFlags(&s_join, cudaEventDisableTiming);
  }

  cudaFuncSetAttribute(gemm_kernel,
                       cudaFuncAttributeMaxDynamicSharedMemorySize, GEMM_SMEM);

  void* cntp = nullptr;
  cudaGetSymbolAddress(&cntp, g_cnt);

  // Fork: side stream = memset + placement
  cudaEventRecord(s_fork, 0);
  cudaStreamWaitEvent(s_side, s_fork, 0);
  cudaMemsetAsync(cntp, 0, (NNP + 1) * sizeof(int), s_side);
  placement_kernel<<<PBLK, 256, 0, s_side>>>(esrc, edst, ew);
  cudaEventRecord(s_join, s_side);

  // Main stream: weight prep + GEMM (independent of placement)
  prep_weights<<<64, 256>>>(weight, res_w);
  gemm_kernel<<<NBLK, 512, GEMM_SMEM>>>(x);

  // Join, then gather
  cudaStreamWaitEvent(0, s_join, 0);
  gather_finalize<<<(NN * 16) / 256, 256>>>(out, bias, gamma, beta, res_b,
                                            esrc, edst, ew);
}